// round 1
// baseline (speedup 1.0000x reference)
#include <cuda_runtime.h>
#include <math.h>

#define HEADS 8
#define DH 32
#define SEQ 64
#define CDIM 256
#define XW_STRIDE 257          // 64 x 257 floats
#define QKV_STRIDE 66          // 2 heads * 32 + 2 pad
#define SIM_STRIDE 65
#define OB_STRIDE 257
#define NTHREADS 512

#define SMEM_FLOATS (SEQ*XW_STRIDE + 3*SEQ*QKV_STRIDE + SEQ*SIM_STRIDE + SEQ*OB_STRIDE)

__global__ void __launch_bounds__(NTHREADS, 1)
local_attn_kernel(const float* __restrict__ x,
                  const float* __restrict__ Wq,
                  const float* __restrict__ Wkv,
                  const float* __restrict__ pos,
                  const float* __restrict__ Wp,
                  const float* __restrict__ bp,
                  float* __restrict__ out)
{
    extern __shared__ float sm[];
    float* xw   = sm;                         // 64*257
    float* qb   = xw + SEQ*XW_STRIDE;         // 64*66 (2 heads)
    float* kb   = qb + SEQ*QKV_STRIDE;
    float* vb   = kb + SEQ*QKV_STRIDE;
    float* simb = vb + SEQ*QKV_STRIDE;        // 64*65
    float* ob   = simb + SEQ*SIM_STRIDE;      // 64*257

    const int t  = threadIdx.x;
    const int wid = blockIdx.x;               // 0..4095
    const int b  = wid >> 10;
    const int nh = (wid >> 5) & 31;
    const int nw = wid & 31;

    // ---------------- Phase A: load window xw (64 x 256) ----------------
    for (int idx = t; idx < SEQ * 64; idx += NTHREADS) {
        int row = idx >> 6;
        int c4  = idx & 63;
        int i = row >> 3, j = row & 7;
        size_t gidx = ((((size_t)(b * 256 + nh * 8 + i)) * 256 + (nw * 8 + j)) << 8) + (c4 << 2);
        float4 v = *(const float4*)(x + gidx);
        float* dst = xw + row * XW_STRIDE + (c4 << 2);
        dst[0] = v.x; dst[1] = v.y; dst[2] = v.z; dst[3] = v.w;
    }
    __syncthreads();

    const float qscale = 0.17677669529663687f;   // 1/sqrt(32)

    // thread mapping for QKV: two heads per batch, 256 threads each
    const int hh_local = t >> 8;                 // 0/1 : head within batch
    const int l = t & 255;
    const int dgq = l & 7;                       // d group -> 4 d's
    const int rgq = l >> 3;                      // 0..31 -> rows rgq*2, rgq*2+1

    // mapping for sim/softmax
    const int si = t >> 3;                       // row 0..63
    const int jlane = t & 7;

    // mapping for attention-out / projection
    const int ar = t >> 3;                       // row 0..63
    const int adg = t & 7;                       // d/col group

    for (int hb = 0; hb < 4; ++hb) {
        // ---------------- Phase B: QKV for heads hb*2, hb*2+1 ----------------
        {
            const int h = hb * 2 + hh_local;
            float aq[2][4] = {}, ak[2][4] = {}, av[2][4] = {};
            const float* wqp = Wq  + h * 32 + dgq * 4;
            const float* wkp = Wkv + h * 32 + dgq * 4;
            const float* wvp = Wkv + 256 + h * 32 + dgq * 4;
            const float* xr0 = xw + (rgq * 2) * XW_STRIDE;
            const float* xr1 = xr0 + XW_STRIDE;
            #pragma unroll 4
            for (int c = 0; c < CDIM; ++c) {
                float x0 = xr0[c];
                float x1 = xr1[c];
                float4 wq = *(const float4*)(wqp + (size_t)c * 256);
                float4 wk = *(const float4*)(wkp + (size_t)c * 512);
                float4 wv = *(const float4*)(wvp + (size_t)c * 512);
                aq[0][0] += x0 * wq.x; aq[0][1] += x0 * wq.y; aq[0][2] += x0 * wq.z; aq[0][3] += x0 * wq.w;
                aq[1][0] += x1 * wq.x; aq[1][1] += x1 * wq.y; aq[1][2] += x1 * wq.z; aq[1][3] += x1 * wq.w;
                ak[0][0] += x0 * wk.x; ak[0][1] += x0 * wk.y; ak[0][2] += x0 * wk.z; ak[0][3] += x0 * wk.w;
                ak[1][0] += x1 * wk.x; ak[1][1] += x1 * wk.y; ak[1][2] += x1 * wk.z; ak[1][3] += x1 * wk.w;
                av[0][0] += x0 * wv.x; av[0][1] += x0 * wv.y; av[0][2] += x0 * wv.z; av[0][3] += x0 * wv.w;
                av[1][0] += x1 * wv.x; av[1][1] += x1 * wv.y; av[1][2] += x1 * wv.z; av[1][3] += x1 * wv.w;
            }
            const int coff = hh_local * 32 + dgq * 4;
            #pragma unroll
            for (int rr = 0; rr < 2; ++rr) {
                const int row = rgq * 2 + rr;
                float* qd = qb + row * QKV_STRIDE + coff;
                float* kd = kb + row * QKV_STRIDE + coff;
                float* vd = vb + row * QKV_STRIDE + coff;
                #pragma unroll
                for (int k = 0; k < 4; ++k) {
                    qd[k] = aq[rr][k] * qscale;
                    kd[k] = ak[rr][k];
                    vd[k] = av[rr][k];
                }
            }
        }
        __syncthreads();

        // ---------------- Phase C/D: attention for each head in batch ----------------
        for (int hh = 0; hh < 2; ++hh) {
            const int hcur = hb * 2 + hh;
            // ---- sim = q k^T + pos, softmax ----
            {
                float qreg[32];
                const float* qrow = qb + si * QKV_STRIDE + hh * 32;
                #pragma unroll
                for (int d = 0; d < 32; ++d) qreg[d] = qrow[d];
                float s[8];
                #pragma unroll
                for (int jj = 0; jj < 8; ++jj) {
                    const int j = jlane + jj * 8;
                    const float* krow = kb + j * QKV_STRIDE + hh * 32;
                    float acc = 0.f;
                    #pragma unroll
                    for (int d = 0; d < 32; ++d) acc += qreg[d] * krow[d];
                    s[jj] = acc + __ldg(pos + (size_t)hcur * 4096 + si * 64 + j);
                }
                // softmax over 64 (8 per lane x 8 lanes)
                float mx = s[0];
                #pragma unroll
                for (int jj = 1; jj < 8; ++jj) mx = fmaxf(mx, s[jj]);
                #pragma unroll
                for (int o = 1; o < 8; o <<= 1) mx = fmaxf(mx, __shfl_xor_sync(0xffffffffu, mx, o));
                float sum = 0.f;
                #pragma unroll
                for (int jj = 0; jj < 8; ++jj) { s[jj] = __expf(s[jj] - mx); sum += s[jj]; }
                #pragma unroll
                for (int o = 1; o < 8; o <<= 1) sum += __shfl_xor_sync(0xffffffffu, sum, o);
                float inv = 1.f / sum;
                #pragma unroll
                for (int jj = 0; jj < 8; ++jj) simb[si * SIM_STRIDE + jlane + jj * 8] = s[jj] * inv;
            }
            __syncthreads();

            // ---- out_h = attn @ v ----
            {
                float acc[4] = {0.f, 0.f, 0.f, 0.f};
                const float* srow = simb + ar * SIM_STRIDE;
                const float* vcol = vb + hh * 32 + adg * 4;
                #pragma unroll 4
                for (int j = 0; j < 64; ++j) {
                    float p = srow[j];
                    const float* vr = vcol + j * QKV_STRIDE;
                    acc[0] += p * vr[0];
                    acc[1] += p * vr[1];
                    acc[2] += p * vr[2];
                    acc[3] += p * vr[3];
                }
                float* orow = ob + ar * OB_STRIDE + hcur * 32 + adg * 4;
                orow[0] = acc[0]; orow[1] = acc[1]; orow[2] = acc[2]; orow[3] = acc[3];
            }
            __syncthreads();
        }
    }

    // ---------------- Phase E: projection out = ob @ Wp + bp, un-window ----------------
    {
        float acc[32];
        const float* bpp = bp + adg * 32;
        #pragma unroll
        for (int k = 0; k < 32; ++k) acc[k] = bpp[k];
        const float* orow = ob + ar * OB_STRIDE;
        const float* wpp = Wp + adg * 32;
        #pragma unroll 2
        for (int c = 0; c < CDIM; ++c) {
            float xv = orow[c];
            const float* wr = wpp + (size_t)c * 256;
            #pragma unroll
            for (int k4 = 0; k4 < 8; ++k4) {
                float4 w = *(const float4*)(wr + k4 * 4);
                acc[k4 * 4 + 0] += xv * w.x;
                acc[k4 * 4 + 1] += xv * w.y;
                acc[k4 * 4 + 2] += xv * w.z;
                acc[k4 * 4 + 3] += xv * w.w;
            }
        }
        const int i = ar >> 3, j = ar & 7;
        float* dst = out + ((((size_t)(b * 256 + nh * 8 + i)) * 256 + (nw * 8 + j)) << 8) + adg * 32;
        #pragma unroll
        for (int k4 = 0; k4 < 8; ++k4) {
            *(float4*)(dst + k4 * 4) = make_float4(acc[k4 * 4 + 0], acc[k4 * 4 + 1],
                                                   acc[k4 * 4 + 2], acc[k4 * 4 + 3]);
        }
    }
}

extern "C" void kernel_launch(void* const* d_in, const int* in_sizes, int n_in,
                              void* d_out, int out_size)
{
    const float* x   = (const float*)d_in[0];
    const float* Wq  = (const float*)d_in[1];
    const float* Wkv = (const float*)d_in[2];
    const float* pos = (const float*)d_in[3];
    const float* Wp  = (const float*)d_in[4];
    const float* bp  = (const float*)d_in[5];
    float* out = (float*)d_out;

    const size_t smem = SMEM_FLOATS * sizeof(float);   // 198,912 bytes
    cudaFuncSetAttribute(local_attn_kernel,
                         cudaFuncAttributeMaxDynamicSharedMemorySize, (int)smem);
    local_attn_kernel<<<4096, NTHREADS, smem>>>(x, Wq, Wkv, pos, Wp, bp, out);
}

// round 2
// speedup vs baseline: 3.8318x; 3.8318x over previous
#include <cuda_runtime.h>

#define NT 512
typedef unsigned long long ull;

// ---------- packed f32x2 helpers (Blackwell sm_103a) ----------
__device__ __forceinline__ ull pk(float lo, float hi) {
    ull r; asm("mov.b64 %0,{%1,%2};" : "=l"(r) : "f"(lo), "f"(hi)); return r;
}
__device__ __forceinline__ float2 upk(ull v) {
    float2 f; asm("mov.b64 {%0,%1},%2;" : "=f"(f.x), "=f"(f.y) : "l"(v)); return f;
}
__device__ __forceinline__ ull fma2(ull a, ull b, ull c) {
    ull d; asm("fma.rn.f32x2 %0,%1,%2,%3;" : "=l"(d) : "l"(a), "l"(b), "l"(c)); return d;
}

// smem layout (floats)
#define OFF_XWT 0            // [256][68]  xwT[c][row]
#define OFF_QT  17408        // [64][68]   qT[d_local][i]   (2 heads)
#define OFF_KT  21760        // [64][68]
#define OFF_VB  26112        // [64][64]   vb[j][d_local]
#define OFF_P2  30208        // [2][64][68]
#define OFF_OBT 38912        // [256][68]  obT[c][i]
#define SMEM_FLOATS 56320    // 225,280 bytes

__global__ void __launch_bounds__(NT, 1)
local_attn_kernel(const float* __restrict__ x,
                  const float* __restrict__ Wq,
                  const float* __restrict__ Wkv,
                  const float* __restrict__ pos,
                  const float* __restrict__ Wp,
                  const float* __restrict__ bp,
                  float* __restrict__ out)
{
    extern __shared__ float sm[];
    float* xwT = sm + OFF_XWT;
    float* qT  = sm + OFF_QT;
    float* kT  = sm + OFF_KT;
    float* vb  = sm + OFF_VB;
    float* P2  = sm + OFF_P2;
    float* obT = sm + OFF_OBT;

    const int t   = threadIdx.x;
    const int wid = blockIdx.x;
    const int b  = wid >> 10;
    const int nh = (wid >> 5) & 31;
    const int nw = wid & 31;

    const float* xbase = x + (((b * 256 + nh * 8) * 256 + nw * 8) << 8);

    // ---------------- Phase A: load + transpose window into xwT[c][row] ----------------
    {
        const int c  = t & 255;
        const int r0 = t >> 8;           // 0,1
        #pragma unroll
        for (int rep = 0; rep < 32; ++rep) {
            int row = r0 + rep * 2;
            int i = row >> 3, j = row & 7;
            float v = __ldg(xbase + i * 65536 + j * 256 + c);
            xwT[c * 68 + row] = v;
        }
    }
    __syncthreads();

    // thread mappings
    const int rg = t >> 6;      // 0..7  (QKV / proj row group: rows rg*8..rg*8+7)
    const int cg = t & 63;      // 0..63 (QKV / proj col)
    const int sh   = t >> 8;        // 0/1 head-local (sim/av)
    const int sidx = t & 255;
    const int sig  = sidx >> 3;     // 0..31 (sim: rows sig*2, sig*2+1)
    const int sjg  = sidx & 7;      // 0..7  (sim: cols sjg*8..+7)
    const int aig  = sidx >> 2;     // 0..63 (av: row)
    const int adg  = sidx & 3;      // 0..3  (av: cols adg*8..+7)

    const float qscale = 0.17677669529663687f;

    for (int hb = 0; hb < 4; ++hb) {
        // ---------------- QKV: C[64 x 192] = xw @ [Wq|Wk|Wv] (2 heads) ----------------
        {
            ull aq[4], ak[4], avv[4];
            #pragma unroll
            for (int i = 0; i < 4; ++i) { aq[i] = 0ULL; ak[i] = 0ULL; avv[i] = 0ULL; }
            const float* wqp = Wq  + hb * 64 + cg;
            const float* wkp = Wkv + hb * 64 + cg;
            const float* wvp = Wkv + 256 + hb * 64 + cg;
            const float* xp  = xwT + rg * 8;
            #pragma unroll 4
            for (int c = 0; c < 256; ++c) {
                float wq = __ldg(wqp + c * 256);
                float wk = __ldg(wkp + c * 512);
                float wv = __ldg(wvp + c * 512);
                ull bq = pk(wq, wq), bk = pk(wk, wk), bv = pk(wv, wv);
                ulonglong2 xa = *(const ulonglong2*)(xp + c * 68);
                ulonglong2 xb = *(const ulonglong2*)(xp + c * 68 + 4);
                aq[0] = fma2(xa.x, bq, aq[0]);  ak[0] = fma2(xa.x, bk, ak[0]);  avv[0] = fma2(xa.x, bv, avv[0]);
                aq[1] = fma2(xa.y, bq, aq[1]);  ak[1] = fma2(xa.y, bk, ak[1]);  avv[1] = fma2(xa.y, bv, avv[1]);
                aq[2] = fma2(xb.x, bq, aq[2]);  ak[2] = fma2(xb.x, bk, ak[2]);  avv[2] = fma2(xb.x, bv, avv[2]);
                aq[3] = fma2(xb.y, bq, aq[3]);  ak[3] = fma2(xb.y, bk, ak[3]);  avv[3] = fma2(xb.y, bv, avv[3]);
            }
            #pragma unroll
            for (int p = 0; p < 4; ++p) {
                float2 fq = upk(aq[p]);
                float2 fk = upk(ak[p]);
                float2 fv = upk(avv[p]);
                int r = rg * 8 + p * 2;
                qT[cg * 68 + r]     = fq.x * qscale;
                qT[cg * 68 + r + 1] = fq.y * qscale;
                kT[cg * 68 + r]     = fk.x;
                kT[cg * 68 + r + 1] = fk.y;
                vb[r * 64 + cg]       = fv.x;
                vb[(r + 1) * 64 + cg] = fv.y;
            }
        }
        __syncthreads();

        // ---------------- sim = q k^T + pos ; softmax ----------------
        {
            const int hq = sh * 32;
            ull s0[4], s1[4];
            #pragma unroll
            for (int i = 0; i < 4; ++i) { s0[i] = 0ULL; s1[i] = 0ULL; }
            #pragma unroll 4
            for (int d = 0; d < 32; ++d) {
                float2 qv = *(const float2*)(qT + (hq + d) * 68 + sig * 2);
                ull q0 = pk(qv.x, qv.x);
                ull q1 = pk(qv.y, qv.y);
                const float* kr = kT + (hq + d) * 68 + sjg * 8;
                ulonglong2 ka = *(const ulonglong2*)(kr);
                ulonglong2 kb = *(const ulonglong2*)(kr + 4);
                s0[0] = fma2(q0, ka.x, s0[0]);  s1[0] = fma2(q1, ka.x, s1[0]);
                s0[1] = fma2(q0, ka.y, s0[1]);  s1[1] = fma2(q1, ka.y, s1[1]);
                s0[2] = fma2(q0, kb.x, s0[2]);  s1[2] = fma2(q1, kb.x, s1[2]);
                s0[3] = fma2(q0, kb.y, s0[3]);  s1[3] = fma2(q1, kb.y, s1[3]);
            }
            const int i0 = sig * 2;
            const int hcur = hb * 2 + sh;
            const float* pp = pos + hcur * 4096 + i0 * 64 + sjg * 8;
            float sv0[8], sv1[8];
            #pragma unroll
            for (int p = 0; p < 4; ++p) {
                float2 f0 = upk(s0[p]); sv0[p * 2] = f0.x; sv0[p * 2 + 1] = f0.y;
                float2 f1 = upk(s1[p]); sv1[p * 2] = f1.x; sv1[p * 2 + 1] = f1.y;
            }
            #pragma unroll
            for (int jj = 0; jj < 8; ++jj) {
                sv0[jj] += __ldg(pp + jj);
                sv1[jj] += __ldg(pp + 64 + jj);
            }
            float m0 = sv0[0], m1 = sv1[0];
            #pragma unroll
            for (int jj = 1; jj < 8; ++jj) { m0 = fmaxf(m0, sv0[jj]); m1 = fmaxf(m1, sv1[jj]); }
            #pragma unroll
            for (int o = 1; o < 8; o <<= 1) {
                m0 = fmaxf(m0, __shfl_xor_sync(0xffffffffu, m0, o));
                m1 = fmaxf(m1, __shfl_xor_sync(0xffffffffu, m1, o));
            }
            float su0 = 0.f, su1 = 0.f;
            #pragma unroll
            for (int jj = 0; jj < 8; ++jj) {
                sv0[jj] = __expf(sv0[jj] - m0); su0 += sv0[jj];
                sv1[jj] = __expf(sv1[jj] - m1); su1 += sv1[jj];
            }
            #pragma unroll
            for (int o = 1; o < 8; o <<= 1) {
                su0 += __shfl_xor_sync(0xffffffffu, su0, o);
                su1 += __shfl_xor_sync(0xffffffffu, su1, o);
            }
            float inv0 = 1.f / su0, inv1 = 1.f / su1;
            float* pr = P2 + sh * 4352 + i0 * 68 + sjg * 8;
            *(float4*)(pr)          = make_float4(sv0[0]*inv0, sv0[1]*inv0, sv0[2]*inv0, sv0[3]*inv0);
            *(float4*)(pr + 4)      = make_float4(sv0[4]*inv0, sv0[5]*inv0, sv0[6]*inv0, sv0[7]*inv0);
            *(float4*)(pr + 68)     = make_float4(sv1[0]*inv1, sv1[1]*inv1, sv1[2]*inv1, sv1[3]*inv1);
            *(float4*)(pr + 68 + 4) = make_float4(sv1[4]*inv1, sv1[5]*inv1, sv1[6]*inv1, sv1[7]*inv1);
        }
        __syncthreads();

        // ---------------- av: out_h = P @ V ----------------
        {
            ull o[4] = {0ULL, 0ULL, 0ULL, 0ULL};
            const float* pr = P2 + sh * 4352 + aig * 68;
            const float* vp = vb + sh * 32 + adg * 8;
            #pragma unroll 4
            for (int j = 0; j < 64; ++j) {
                float p = pr[j];
                ull pb = pk(p, p);
                ulonglong2 va = *(const ulonglong2*)(vp + j * 64);
                ulonglong2 vbq = *(const ulonglong2*)(vp + j * 64 + 4);
                o[0] = fma2(pb, va.x, o[0]);
                o[1] = fma2(pb, va.y, o[1]);
                o[2] = fma2(pb, vbq.x, o[2]);
                o[3] = fma2(pb, vbq.y, o[3]);
            }
            const int dbase = (hb * 2 + sh) * 32 + adg * 8;
            #pragma unroll
            for (int p = 0; p < 4; ++p) {
                float2 f = upk(o[p]);
                obT[(dbase + p * 2) * 68 + aig]     = f.x;
                obT[(dbase + p * 2 + 1) * 68 + aig] = f.y;
            }
        }
        __syncthreads();
    }

    // ---------------- Projection: out = obT^T @ Wp + bp ----------------
    {
        ull acc[4][4];   // [col][row-pair]
        #pragma unroll
        for (int a = 0; a < 4; ++a)
            #pragma unroll
            for (int p = 0; p < 4; ++p) acc[a][p] = 0ULL;
        const float* wpp = Wp + cg * 4;
        const float* op  = obT + rg * 8;
        #pragma unroll 2
        for (int c = 0; c < 256; ++c) {
            float4 w = __ldg((const float4*)(wpp + c * 256));
            ull w0 = pk(w.x, w.x), w1 = pk(w.y, w.y), w2 = pk(w.z, w.z), w3 = pk(w.w, w.w);
            ulonglong2 xa = *(const ulonglong2*)(op + c * 68);
            ulonglong2 xb = *(const ulonglong2*)(op + c * 68 + 4);
            acc[0][0] = fma2(xa.x, w0, acc[0][0]);  acc[1][0] = fma2(xa.x, w1, acc[1][0]);
            acc[2][0] = fma2(xa.x, w2, acc[2][0]);  acc[3][0] = fma2(xa.x, w3, acc[3][0]);
            acc[0][1] = fma2(xa.y, w0, acc[0][1]);  acc[1][1] = fma2(xa.y, w1, acc[1][1]);
            acc[2][1] = fma2(xa.y, w2, acc[2][1]);  acc[3][1] = fma2(xa.y, w3, acc[3][1]);
            acc[0][2] = fma2(xb.x, w0, acc[0][2]);  acc[1][2] = fma2(xb.x, w1, acc[1][2]);
            acc[2][2] = fma2(xb.x, w2, acc[2][2]);  acc[3][2] = fma2(xb.x, w3, acc[3][2]);
            acc[0][3] = fma2(xb.y, w0, acc[0][3]);  acc[1][3] = fma2(xb.y, w1, acc[1][3]);
            acc[2][3] = fma2(xb.y, w2, acc[2][3]);  acc[3][3] = fma2(xb.y, w3, acc[3][3]);
        }
        float4 bias = __ldg((const float4*)(bp + cg * 4));
        float* obase = out + (((b * 256 + nh * 8) * 256 + nw * 8) << 8) + cg * 4;
        #pragma unroll
        for (int p = 0; p < 4; ++p) {
            float2 c0 = upk(acc[0][p]);
            float2 c1 = upk(acc[1][p]);
            float2 c2 = upk(acc[2][p]);
            float2 c3 = upk(acc[3][p]);
            int r = rg * 8 + p * 2;
            int i = r >> 3, j = r & 7;
            *(float4*)(obase + i * 65536 + j * 256) =
                make_float4(c0.x + bias.x, c1.x + bias.y, c2.x + bias.z, c3.x + bias.w);
            r = r + 1; i = r >> 3; j = r & 7;
            *(float4*)(obase + i * 65536 + j * 256) =
                make_float4(c0.y + bias.x, c1.y + bias.y, c2.y + bias.z, c3.y + bias.w);
        }
    }
}

extern "C" void kernel_launch(void* const* d_in, const int* in_sizes, int n_in,
                              void* d_out, int out_size)
{
    const float* x   = (const float*)d_in[0];
    const float* Wq  = (const float*)d_in[1];
    const float* Wkv = (const float*)d_in[2];
    const float* pos = (const float*)d_in[3];
    const float* Wp  = (const float*)d_in[4];
    const float* bp  = (const float*)d_in[5];
    float* out = (float*)d_out;

    const size_t smem = SMEM_FLOATS * sizeof(float);   // 225,280 bytes
    cudaFuncSetAttribute(local_attn_kernel,
                         cudaFuncAttributeMaxDynamicSharedMemorySize, (int)smem);
    local_attn_kernel<<<4096, NT, smem>>>(x, Wq, Wkv, pos, Wp, bp, out);
}

// round 3
// speedup vs baseline: 3.8437x; 1.0031x over previous
#include <cuda_runtime.h>

#define NT 512
typedef unsigned long long ull;

// ---------- packed f32x2 helpers (Blackwell sm_103a) ----------
__device__ __forceinline__ ull pk(float lo, float hi) {
    ull r; asm("mov.b64 %0,{%1,%2};" : "=l"(r) : "f"(lo), "f"(hi)); return r;
}
__device__ __forceinline__ float2 upk(ull v) {
    float2 f; asm("mov.b64 {%0,%1},%2;" : "=f"(f.x), "=f"(f.y) : "l"(v)); return f;
}
__device__ __forceinline__ ull fma2(ull a, ull b, ull c) {
    ull d; asm("fma.rn.f32x2 %0,%1,%2,%3;" : "=l"(d) : "l"(a), "l"(b), "l"(c)); return d;
}

// smem layout (floats)
#define OFF_XWT 0            // [256][68]  xwT[c][row]
#define OFF_QT  17408        // [64][68]   qT[d_local][i]   (2 heads)
#define OFF_KT  21760        // [64][68]
#define OFF_VB  26112        // [64][64]   vb[j][d_local]
#define OFF_P2  30208        // [2][64][68]
#define OFF_OBT 38912        // [256][68]  obT[c][i]
#define SMEM_FLOATS 56320    // 225,280 bytes

__global__ void __launch_bounds__(NT, 1)
local_attn_kernel(const float* __restrict__ x,
                  const float* __restrict__ Wq,
                  const float* __restrict__ Wkv,
                  const float* __restrict__ pos,
                  const float* __restrict__ Wp,
                  const float* __restrict__ bp,
                  float* __restrict__ out)
{
    extern __shared__ float sm[];
    float* xwT = sm + OFF_XWT;
    float* qT  = sm + OFF_QT;
    float* kT  = sm + OFF_KT;
    float* vb  = sm + OFF_VB;
    float* P2  = sm + OFF_P2;
    float* obT = sm + OFF_OBT;

    const int t   = threadIdx.x;
    const int wid = blockIdx.x;
    const int b  = wid >> 10;
    const int nh = (wid >> 5) & 31;
    const int nw = wid & 31;

    const float* xbase = x + (((b * 256 + nh * 8) * 256 + nw * 8) << 8);

    // ---------------- Phase A: load + transpose window into xwT[c][row] ----------------
    {
        const int c  = t & 255;
        const int r0 = t >> 8;           // 0,1
        #pragma unroll
        for (int rep = 0; rep < 32; ++rep) {
            int row = r0 + rep * 2;
            int i = row >> 3, j = row & 7;
            float v = __ldg(xbase + i * 65536 + j * 256 + c);
            xwT[c * 68 + row] = v;
        }
    }
    __syncthreads();

    // thread mappings
    const int rg = t >> 6;      // 0..7  (QKV / proj row group: rows rg*8..rg*8+7)
    const int cg = t & 63;      // 0..63 (QKV / proj col)
    const int sh   = t >> 8;        // 0/1 head-local (sim/av)
    const int sidx = t & 255;
    const int sig  = sidx >> 3;     // 0..31 (sim: rows sig*2, sig*2+1)
    const int sjg  = sidx & 7;      // 0..7  (sim: cols sjg*8..+7)
    const int aig  = sidx >> 2;     // 0..63 (av: row)
    const int adg  = sidx & 3;      // 0..3  (av: cols adg*8..+7)

    const float qscale = 0.17677669529663687f;

    for (int hb = 0; hb < 4; ++hb) {
        // ---------------- QKV: C[64 x 192] = xw @ [Wq|Wk|Wv] (2 heads) ----------------
        {
            ull aq[4], ak[4], avv[4];
            #pragma unroll
            for (int i = 0; i < 4; ++i) { aq[i] = 0ULL; ak[i] = 0ULL; avv[i] = 0ULL; }
            const float* wqp = Wq  + hb * 64 + cg;
            const float* wkp = Wkv + hb * 64 + cg;
            const float* wvp = Wkv + 256 + hb * 64 + cg;
            const float* xp  = xwT + rg * 8;
            #pragma unroll 4
            for (int c = 0; c < 256; ++c) {
                float wq = __ldg(wqp + c * 256);
                float wk = __ldg(wkp + c * 512);
                float wv = __ldg(wvp + c * 512);
                ull bq = pk(wq, wq), bk = pk(wk, wk), bv = pk(wv, wv);
                ulonglong2 xa = *(const ulonglong2*)(xp + c * 68);
                ulonglong2 xb = *(const ulonglong2*)(xp + c * 68 + 4);
                aq[0] = fma2(xa.x, bq, aq[0]);  ak[0] = fma2(xa.x, bk, ak[0]);  avv[0] = fma2(xa.x, bv, avv[0]);
                aq[1] = fma2(xa.y, bq, aq[1]);  ak[1] = fma2(xa.y, bk, ak[1]);  avv[1] = fma2(xa.y, bv, avv[1]);
                aq[2] = fma2(xb.x, bq, aq[2]);  ak[2] = fma2(xb.x, bk, ak[2]);  avv[2] = fma2(xb.x, bv, avv[2]);
                aq[3] = fma2(xb.y, bq, aq[3]);  ak[3] = fma2(xb.y, bk, ak[3]);  avv[3] = fma2(xb.y, bv, avv[3]);
            }
            #pragma unroll
            for (int p = 0; p < 4; ++p) {
                float2 fq = upk(aq[p]);
                float2 fk = upk(ak[p]);
                float2 fv = upk(avv[p]);
                int r = rg * 8 + p * 2;
                qT[cg * 68 + r]     = fq.x * qscale;
                qT[cg * 68 + r + 1] = fq.y * qscale;
                kT[cg * 68 + r]     = fk.x;
                kT[cg * 68 + r + 1] = fk.y;
                vb[r * 64 + cg]       = fv.x;
                vb[(r + 1) * 64 + cg] = fv.y;
            }
        }
        __syncthreads();

        // ---------------- sim = q k^T + pos ; softmax ----------------
        {
            const int hq = sh * 32;
            ull s0[4], s1[4];
            #pragma unroll
            for (int i = 0; i < 4; ++i) { s0[i] = 0ULL; s1[i] = 0ULL; }
            #pragma unroll 4
            for (int d = 0; d < 32; ++d) {
                float2 qv = *(const float2*)(qT + (hq + d) * 68 + sig * 2);
                ull q0 = pk(qv.x, qv.x);
                ull q1 = pk(qv.y, qv.y);
                const float* kr = kT + (hq + d) * 68 + sjg * 8;
                ulonglong2 ka = *(const ulonglong2*)(kr);
                ulonglong2 kb = *(const ulonglong2*)(kr + 4);
                s0[0] = fma2(q0, ka.x, s0[0]);  s1[0] = fma2(q1, ka.x, s1[0]);
                s0[1] = fma2(q0, ka.y, s0[1]);  s1[1] = fma2(q1, ka.y, s1[1]);
                s0[2] = fma2(q0, kb.x, s0[2]);  s1[2] = fma2(q1, kb.x, s1[2]);
                s0[3] = fma2(q0, kb.y, s0[3]);  s1[3] = fma2(q1, kb.y, s1[3]);
            }
            const int i0 = sig * 2;
            const int hcur = hb * 2 + sh;
            const float* pp = pos + hcur * 4096 + i0 * 64 + sjg * 8;
            float sv0[8], sv1[8];
            #pragma unroll
            for (int p = 0; p < 4; ++p) {
                float2 f0 = upk(s0[p]); sv0[p * 2] = f0.x; sv0[p * 2 + 1] = f0.y;
                float2 f1 = upk(s1[p]); sv1[p * 2] = f1.x; sv1[p * 2 + 1] = f1.y;
            }
            #pragma unroll
            for (int jj = 0; jj < 8; ++jj) {
                sv0[jj] += __ldg(pp + jj);
                sv1[jj] += __ldg(pp + 64 + jj);
            }
            float m0 = sv0[0], m1 = sv1[0];
            #pragma unroll
            for (int jj = 1; jj < 8; ++jj) { m0 = fmaxf(m0, sv0[jj]); m1 = fmaxf(m1, sv1[jj]); }
            #pragma unroll
            for (int o = 1; o < 8; o <<= 1) {
                m0 = fmaxf(m0, __shfl_xor_sync(0xffffffffu, m0, o));
                m1 = fmaxf(m1, __shfl_xor_sync(0xffffffffu, m1, o));
            }
            float su0 = 0.f, su1 = 0.f;
            #pragma unroll
            for (int jj = 0; jj < 8; ++jj) {
                sv0[jj] = __expf(sv0[jj] - m0); su0 += sv0[jj];
                sv1[jj] = __expf(sv1[jj] - m1); su1 += sv1[jj];
            }
            #pragma unroll
            for (int o = 1; o < 8; o <<= 1) {
                su0 += __shfl_xor_sync(0xffffffffu, su0, o);
                su1 += __shfl_xor_sync(0xffffffffu, su1, o);
            }
            float inv0 = 1.f / su0, inv1 = 1.f / su1;
            float* pr = P2 + sh * 4352 + i0 * 68 + sjg * 8;
            *(float4*)(pr)          = make_float4(sv0[0]*inv0, sv0[1]*inv0, sv0[2]*inv0, sv0[3]*inv0);
            *(float4*)(pr + 4)      = make_float4(sv0[4]*inv0, sv0[5]*inv0, sv0[6]*inv0, sv0[7]*inv0);
            *(float4*)(pr + 68)     = make_float4(sv1[0]*inv1, sv1[1]*inv1, sv1[2]*inv1, sv1[3]*inv1);
            *(float4*)(pr + 68 + 4) = make_float4(sv1[4]*inv1, sv1[5]*inv1, sv1[6]*inv1, sv1[7]*inv1);
        }
        __syncthreads();

        // ---------------- av: out_h = P @ V ----------------
        {
            ull o[4] = {0ULL, 0ULL, 0ULL, 0ULL};
            const float* pr = P2 + sh * 4352 + aig * 68;
            const float* vp = vb + sh * 32 + adg * 8;
            #pragma unroll 4
            for (int j = 0; j < 64; ++j) {
                float p = pr[j];
                ull pb = pk(p, p);
                ulonglong2 va = *(const ulonglong2*)(vp + j * 64);
                ulonglong2 vbq = *(const ulonglong2*)(vp + j * 64 + 4);
                o[0] = fma2(pb, va.x, o[0]);
                o[1] = fma2(pb, va.y, o[1]);
                o[2] = fma2(pb, vbq.x, o[2]);
                o[3] = fma2(pb, vbq.y, o[3]);
            }
            const int dbase = (hb * 2 + sh) * 32 + adg * 8;
            #pragma unroll
            for (int p = 0; p < 4; ++p) {
                float2 f = upk(o[p]);
                obT[(dbase + p * 2) * 68 + aig]     = f.x;
                obT[(dbase + p * 2 + 1) * 68 + aig] = f.y;
            }
        }
        __syncthreads();
    }

    // ---------------- Projection: out = obT^T @ Wp + bp ----------------
    {
        ull acc[4][4];   // [col][row-pair]
        #pragma unroll
        for (int a = 0; a < 4; ++a)
            #pragma unroll
            for (int p = 0; p < 4; ++p) acc[a][p] = 0ULL;
        const float* wpp = Wp + cg * 4;
        const float* op  = obT + rg * 8;
        #pragma unroll 2
        for (int c = 0; c < 256; ++c) {
            float4 w = __ldg((const float4*)(wpp + c * 256));
            ull w0 = pk(w.x, w.x), w1 = pk(w.y, w.y), w2 = pk(w.z, w.z), w3 = pk(w.w, w.w);
            ulonglong2 xa = *(const ulonglong2*)(op + c * 68);
            ulonglong2 xb = *(const ulonglong2*)(op + c * 68 + 4);
            acc[0][0] = fma2(xa.x, w0, acc[0][0]);  acc[1][0] = fma2(xa.x, w1, acc[1][0]);
            acc[2][0] = fma2(xa.x, w2, acc[2][0]);  acc[3][0] = fma2(xa.x, w3, acc[3][0]);
            acc[0][1] = fma2(xa.y, w0, acc[0][1]);  acc[1][1] = fma2(xa.y, w1, acc[1][1]);
            acc[2][1] = fma2(xa.y, w2, acc[2][1]);  acc[3][1] = fma2(xa.y, w3, acc[3][1]);
            acc[0][2] = fma2(xb.x, w0, acc[0][2]);  acc[1][2] = fma2(xb.x, w1, acc[1][2]);
            acc[2][2] = fma2(xb.x, w2, acc[2][2]);  acc[3][2] = fma2(xb.x, w3, acc[3][2]);
            acc[0][3] = fma2(xb.y, w0, acc[0][3]);  acc[1][3] = fma2(xb.y, w1, acc[1][3]);
            acc[2][3] = fma2(xb.y, w2, acc[2][3]);  acc[3][3] = fma2(xb.y, w3, acc[3][3]);
        }
        float4 bias = __ldg((const float4*)(bp + cg * 4));
        float* obase = out + (((b * 256 + nh * 8) * 256 + nw * 8) << 8) + cg * 4;
        #pragma unroll
        for (int p = 0; p < 4; ++p) {
            float2 c0 = upk(acc[0][p]);
            float2 c1 = upk(acc[1][p]);
            float2 c2 = upk(acc[2][p]);
            float2 c3 = upk(acc[3][p]);
            int r = rg * 8 + p * 2;
            int i = r >> 3, j = r & 7;
            *(float4*)(obase + i * 65536 + j * 256) =
                make_float4(c0.x + bias.x, c1.x + bias.y, c2.x + bias.z, c3.x + bias.w);
            r = r + 1; i = r >> 3; j = r & 7;
            *(float4*)(obase + i * 65536 + j * 256) =
                make_float4(c0.y + bias.x, c1.y + bias.y, c2.y + bias.z, c3.y + bias.w);
        }
    }
}

extern "C" void kernel_launch(void* const* d_in, const int* in_sizes, int n_in,
                              void* d_out, int out_size)
{
    const float* x   = (const float*)d_in[0];
    const float* Wq  = (const float*)d_in[1];
    const float* Wkv = (const float*)d_in[2];
    const float* pos = (const float*)d_in[3];
    const float* Wp  = (const float*)d_in[4];
    const float* bp  = (const float*)d_in[5];
    float* out = (float*)d_out;

    const size_t smem = SMEM_FLOATS * sizeof(float);   // 225,280 bytes
    cudaFuncSetAttribute(local_attn_kernel,
                         cudaFuncAttributeMaxDynamicSharedMemorySize, (int)smem);
    local_attn_kernel<<<4096, NT, smem>>>(x, Wq, Wkv, pos, Wp, bp, out);
}